// round 15
// baseline (speedup 1.0000x reference)
#include <cuda_runtime.h>
#include <cuda_fp16.h>
#include <mma.h>
#include <math.h>
#include <stdint.h>

using namespace nvcuda;

// Problem constants
#define NN 100000
#define NNP 100096          // padded to multiple of 128 for unguarded tile stores
#define EE 200000
#define BB 2048
#define DD 256
#define LL 5
#define HID 512
#define BN_EPS 1e-5f
#define AGG_NPB 8
#define MTILES (NNP / 128)  // 782
#define PERSIST_GRID 304    // 2 CTAs/SM x 152 SMs (extra CTAs exit instantly)

// ---------------- scratch (device globals; no allocation allowed) ------------
__device__ __half g_hh[(size_t)NNP * DD];          // layer-0 node features (half)
__device__ __half g_zh[(size_t)NNP * DD];          // z (GEMM2 out, half)
__device__ __half g_aggh[(size_t)NNP * DD];        // GEMM1 input (half)
__device__ __half g_t1h[(size_t)NNP * HID];        // GEMM2 input (half)
__device__ __half g_w1h[(size_t)LL * HID * DD];    // [l][n][k] = W1[l][k][n]
__device__ __half g_w2h[(size_t)LL * DD * HID];    // [l][n][k] = W2[l][k][n]
__device__ int    g_deg[NN];
__device__ int    g_rowptr[NN + 1];
__device__ int    g_cursor[NN];
__device__ int    g_epack[EE];                     // src<<4 | (bt*3+bd), sorted per segment
__device__ int    g_tick[2 * LL];                  // persistent-GEMM tile tickets
__device__ float  g_partial2[(size_t)MTILES * 2 * DD];
__device__ float  g_stats[2 * DD];                 // [0:256)=a, [256:512)=c
__device__ float  g_pooled[BB * DD];

static __device__ __forceinline__ uint32_t smem_u32(const void* p) {
    uint32_t a;
    asm("{ .reg .u64 t; cvta.to.shared.u64 t, %1; cvt.u32.u64 %0, t; }" : "=r"(a) : "l"(p));
    return a;
}
static __device__ __forceinline__ void cp16(uint32_t dst, const void* src) {
    asm volatile("cp.async.cg.shared.global [%0], [%1], 16;" :: "r"(dst), "l"(src));
}
#define CP_COMMIT() asm volatile("cp.async.commit_group;" ::: "memory")
#define CP_WAIT(n)  asm volatile("cp.async.wait_group %0;" :: "n"(n) : "memory")

// ---------------- CSR build ----------------
__global__ void k_zero_deg() {
    int i = blockIdx.x * blockDim.x + threadIdx.x;
    if (i < NN) g_deg[i] = 0;
    if (i < 2 * LL) g_tick[i] = 0;
}

__global__ void k_hist(const int* __restrict__ edge_index) {
    int e = blockIdx.x * blockDim.x + threadIdx.x;
    if (e < EE) atomicAdd(&g_deg[edge_index[EE + e]], 1);
}

// exclusive scan: deg -> rowptr, and cursor = rowptr[i]
__global__ void k_scan() {
    __shared__ int s[1024];
    __shared__ int carry;
    int tid = threadIdx.x;
    if (tid == 0) { carry = 0; g_rowptr[0] = 0; }
    __syncthreads();
    for (int base = 0; base < NN; base += 1024) {
        int i = base + tid;
        int v = (i < NN) ? g_deg[i] : 0;
        s[tid] = v;
        __syncthreads();
        for (int off = 1; off < 1024; off <<= 1) {
            int t = (tid >= off) ? s[tid - off] : 0;
            __syncthreads();
            s[tid] += t;
            __syncthreads();
        }
        if (i < NN) {
            g_rowptr[i + 1] = carry + s[tid];
            g_cursor[i] = carry + s[tid] - v;
        }
        __syncthreads();
        if (tid == 0) carry += s[1023];
        __syncthreads();
    }
}

// scatter packed records directly (order nondeterministic; fixed by value sort)
__global__ void k_scatter(const int* __restrict__ edge_index,
                          const int* __restrict__ edge_attr) {
    int e = blockIdx.x * blockDim.x + threadIdx.x;
    if (e < EE) {
        int dstn = edge_index[EE + e];
        int sn = edge_index[e];
        int bt = edge_attr[e * 2 + 0];
        int bd = edge_attr[e * 2 + 1];
        int pos = atomicAdd(&g_cursor[dstn], 1);
        g_epack[pos] = (sn << 4) | (bt * 3 + bd);
    }
}

// deterministic order: sort packed values within each segment
__global__ void k_sortseg() {
    int i = blockIdx.x * blockDim.x + threadIdx.x;
    if (i >= NN) return;
    int s = g_rowptr[i], e = g_rowptr[i + 1];
    for (int a = s + 1; a < e; a++) {
        int v = g_epack[a];
        int b = a - 1;
        while (b >= s && g_epack[b] > v) { g_epack[b + 1] = g_epack[b]; b--; }
        g_epack[b + 1] = v;
    }
}

// ---------------- weight transpose -> half ----------------
__global__ void k_prep_w1h(const float* __restrict__ W1) {
    int idx = blockIdx.x * blockDim.x + threadIdx.x;
    if (idx >= LL * HID * DD) return;
    int l = idx / (HID * DD);
    int rem = idx - l * (HID * DD);
    int n = rem / DD;
    int k = rem - n * DD;
    g_w1h[idx] = __float2half_rn(W1[(size_t)l * DD * HID + (size_t)k * HID + n]);
}

__global__ void k_prep_w2h(const float* __restrict__ W2) {
    int idx = blockIdx.x * blockDim.x + threadIdx.x;
    if (idx >= LL * DD * HID) return;
    int l = idx / (DD * HID);
    int rem = idx - l * (DD * HID);
    int n = rem / HID;
    int k = rem - n * HID;
    g_w2h[idx] = __float2half_rn(W2[(size_t)l * HID * DD + (size_t)k * DD + n]);
}

// ---------------- h init (half) ----------------
__global__ void k_init_h(const int* __restrict__ x,
                         const float* __restrict__ emb1,
                         const float* __restrict__ emb2) {
    int i = blockIdx.x;
    int d = threadIdx.x;
    int a = x[i * 2 + 0], c = x[i * 2 + 1];
    g_hh[(size_t)i * DD + d] = __float2half_rn(emb1[a * DD + d] + emb2[c * DD + d]);
}

// ---------------- aggregation: half2, packed edges, optional fused BN -------
// BN==0: reads g_hh raw (layer 0). BN==1: reads g_zh, applies relu(z*a+c).
template<int BN>
__global__ __launch_bounds__(128)
void k_agg(const float* __restrict__ e1, const float* __restrict__ e2) {
    int base = blockIdx.x * AGG_NPB;
    int d2 = threadIdx.x;                 // 0..127 -> features 2*d2, 2*d2+1
    __shared__ float sc[15][DD];          // combined e1[bt]+e2[bd]
    for (int idx = d2; idx < 15 * DD; idx += 128) {
        int c = idx >> 8;                 // 0..14
        int dd = idx & (DD - 1);
        sc[c][dd] = e1[(c / 3) * DD + dd] + e2[(c % 3) * DD + dd];
    }
    __syncthreads();

    const __half2* H2 = BN ? (const __half2*)g_zh : (const __half2*)g_hh;
    __half2* A2 = (__half2*)g_aggh;
    const float2 selfc = *(const float2*)&sc[12][2 * d2];   // bt=4, bd=0

    float2 bna = make_float2(0.f, 0.f), bnc = make_float2(0.f, 0.f);
    if (BN) {
        bna = *(const float2*)&g_stats[2 * d2];
        bnc = *(const float2*)&g_stats[DD + 2 * d2];
    }

    auto loadh = [&](size_t idx) -> float2 {
        __half2 hv = H2[idx];
        float2 v;
        v.x = __low2float(hv);
        v.y = __high2float(hv);
        if (BN) {
            v.x = fmaxf(v.x * bna.x + bnc.x, 0.f);
            v.y = fmaxf(v.y * bna.y + bnc.y, 0.f);
        }
        return v;
    };

#pragma unroll
    for (int j = 0; j < AGG_NPB; j++) {
        int i = base + j;
        if (i >= NN) break;
        float2 hv = loadh((size_t)i * 128 + d2);
        float2 acc;
        acc.x = hv.x + selfc.x;
        acc.y = hv.y + selfc.y;
        int s = g_rowptr[i], e = g_rowptr[i + 1];
        for (int p = s; p < e; p++) {
            int pk = g_epack[p];
            int sn = pk >> 4;
            int c = pk & 15;
            float2 nh = loadh((size_t)sn * 128 + d2);
            float2 scv = *(const float2*)&sc[c][2 * d2];
            acc.x += nh.x + scv.x;
            acc.y += nh.y + scv.y;
        }
        A2[(size_t)i * 128 + d2] = __floats2half2_rn(acc.x, acc.y);
    }
}

// ========== persistent wmma fp16 GEMM, 2-stage cp.async, BK=32 ==============
// BM=128, BN=128, BK=32. 8 warps = 2(M) x 4(N); warp tile 64x32 = 4x2 wmma tiles.
// Proven R11 geometry (HLD=40, 73.7KB, 2 CTAs/SM). Tiles dispatched via atomic
// ticket -> no ragged wave tails, no fixed CTA->tile map (results deterministic:
// tiles write disjoint memory, partials indexed by tile coords).
// G==0: g_t1h = half(relu(g_aggh @ W1h + b1))
// G==1: g_zh = half(g_t1h @ W2h)  + fused column sum/sumsq partials (fp32)
#define HLD 40                             // halfs per SMEM row (32 + pad 8) = 80B
#define STG_HALFS (2 * 128 * HLD)          // A + B per stage = 10240 halfs
#define GEMM_SMEM (2 * STG_HALFS * 2)      // 40960*... = 73728? no: 2*10240*2*... 
#undef GEMM_SMEM
#define GEMM_SMEM (2 * STG_HALFS * 2)      // 40960 B? -> 2*10240 halfs *2B = 40960B... keep explicit:
#undef GEMM_SMEM
#define GEMM_SMEM (2 * STG_HALFS * 2)      // bytes: 2 stages x 10240 halfs x 2B = 40960
#define ELD 68                             // epilogue float tile leading dim

template<int G>
__global__ __launch_bounds__(256, 2)
void gemm_wmma(const float* __restrict__ bias, int l) {
    constexpr int K  = (G == 0) ? DD : HID;
    constexpr int NC = (G == 0) ? HID : DD;
    constexpr int NIT = K / 32;            // 8 or 16
    constexpr int NX  = NC / 128;          // 4 or 2
    const int NT = NX * MTILES;
    const int slot = l * 2 + G;

    const __half* __restrict__ A = (G == 0) ? (const __half*)g_aggh : (const __half*)g_t1h;
    const __half* __restrict__ BT =
        ((G == 0) ? (const __half*)g_w1h : (const __half*)g_w2h) + (size_t)l * K * NC;

    extern __shared__ __half smh[];
    __shared__ float ps[4][64];
    __shared__ float pq[4][64];
    __shared__ int s_tile;

    const int tid = threadIdx.x;
    const int wid = tid >> 5;
    const int warpM = wid & 1;    // 0..1  (64 rows)
    const int warpN = wid >> 1;   // 0..3  (32 cols)

    // staging: thread t -> row = t>>1 (0..127), 32B segment = (t&1)
    const int row = tid >> 1;
    const int seg = tid & 1;

    const uint32_t smBase = smem_u32(smh);
    const uint32_t smA[2] = { smBase + (uint32_t)(row * HLD + seg * 16) * 2u,
                              smBase + (uint32_t)(STG_HALFS + row * HLD + seg * 16) * 2u };
    const uint32_t smB[2] = { smA[0] + 128u * HLD * 2u, smA[1] + 128u * HLD * 2u };

    while (true) {
        if (tid == 0) s_tile = atomicAdd(&g_tick[slot], 1);
        __syncthreads();
        const int tile = s_tile;
        if (tile >= NT) break;
        const int by = tile / NX;           // adjacent tickets share A row-block -> L2 reuse
        const int bx = tile - by * NX;
        const int m0 = by * 128;
        const int n0 = bx * 128;

        const __half* gA = A  + (size_t)(m0 + row) * K + seg * 16;
        const __half* gB = BT + (size_t)(n0 + row) * K + seg * 16;

        auto issue_stage = [&](int it, int buf) {
            const __half* a = gA + it * 32;
            const __half* b = gB + it * 32;
            cp16(smA[buf],       a);
            cp16(smA[buf] + 16u, a + 8);
            cp16(smB[buf],       b);
            cp16(smB[buf] + 16u, b + 8);
            CP_COMMIT();
        };

        wmma::fragment<wmma::accumulator, 16, 16, 16, float> acc[4][2];
#pragma unroll
        for (int t = 0; t < 4; t++)
#pragma unroll
            for (int u = 0; u < 2; u++) wmma::fill_fragment(acc[t][u], 0.0f);

        issue_stage(0, 0);
        issue_stage(1, 1);

        for (int it = 0; it < NIT; it++) {
            int buf = it & 1;
            if (it == NIT - 1) CP_WAIT(0); else CP_WAIT(1);
            __syncthreads();

            const __half* As = smh + buf * STG_HALFS;
            const __half* Bs = As + 128 * HLD;
#pragma unroll
            for (int ks = 0; ks < 2; ks++) {
                wmma::fragment<wmma::matrix_a, 16, 16, 16, __half, wmma::row_major> af[4];
                wmma::fragment<wmma::matrix_b, 16, 16, 16, __half, wmma::col_major> bf[2];
#pragma unroll
                for (int t = 0; t < 4; t++)
                    wmma::load_matrix_sync(af[t], As + (warpM * 64 + t * 16) * HLD + ks * 16, HLD);
#pragma unroll
                for (int u = 0; u < 2; u++)
                    wmma::load_matrix_sync(bf[u], Bs + (warpN * 32 + u * 16) * HLD + ks * 16, HLD);
#pragma unroll
                for (int t = 0; t < 4; t++)
#pragma unroll
                    for (int u = 0; u < 2; u++)
                        wmma::mma_sync(acc[t][u], af[t], bf[u], acc[t][u]);
            }

            if (it + 2 < NIT) {
                __syncthreads();          // all warps done reading buf before refill
                issue_stage(it + 2, buf);
            }
        }

        // ------ epilogue: 2 passes of 64 columns via SMEM float tile --------
        float* ep = (float*)smh;          // 128 x ELD floats = 34816 B <= GEMM_SMEM
        const int coff = seg * 32;
#pragma unroll
        for (int p = 0; p < 2; p++) {
            __syncthreads();
            if ((warpN >> 1) == p) {
#pragma unroll
                for (int t = 0; t < 4; t++)
#pragma unroll
                    for (int u = 0; u < 2; u++)
                        wmma::store_matrix_sync(
                            ep + (warpM * 64 + t * 16) * ELD + (warpN & 1) * 32 + u * 16,
                            acc[t][u], ELD, wmma::mem_row_major);
            }
            __syncthreads();

            if (G == 0) {
                const float* srow = ep + row * ELD + coff;
                const float* brow = bias + n0 + p * 64 + coff;
                __half2* crow = (__half2*)(g_t1h + (size_t)(m0 + row) * NC + n0 + p * 64 + coff);
#pragma unroll
                for (int i = 0; i < 16; i++) {
                    float2 v = *(const float2*)(srow + 2 * i);
                    float2 bp = *(const float2*)(brow + 2 * i);
                    crow[i] = __floats2half2_rn(fmaxf(v.x + bp.x, 0.f), fmaxf(v.y + bp.y, 0.f));
                }
            } else {
                const float* srow = ep + row * ELD + coff;
                __half2* crow = (__half2*)(g_zh + (size_t)(m0 + row) * NC + n0 + p * 64 + coff);
#pragma unroll
                for (int i = 0; i < 16; i++) {
                    float2 v = *(const float2*)(srow + 2 * i);
                    crow[i] = __floats2half2_rn(v.x, v.y);
                }

                // fused column partials from exact fp32 tile (exclude padding rows)
                const int col = tid & 63;
                const int grp = tid >> 6;
                const int rlim = (NN - m0 < 128) ? (NN - m0) : 128;
                float s = 0.f, q = 0.f;
                for (int r = grp * 32; r < grp * 32 + 32; r++) {
                    if (r >= rlim) break;
                    float v = ep[r * ELD + col];
                    s += v; q += v * v;
                }
                ps[grp][col] = s;
                pq[grp][col] = q;
                __syncthreads();
                if (grp == 0) {
                    float S = ps[0][col] + ps[1][col] + ps[2][col] + ps[3][col];
                    float Q = pq[0][col] + pq[1][col] + pq[2][col] + pq[3][col];
                    int cg = n0 + p * 64 + col;
                    g_partial2[(size_t)by * 2 * DD + cg] = S;
                    g_partial2[(size_t)by * 2 * DD + DD + cg] = Q;
                }
            }
        }
        __syncthreads();   // ep (= staging SMEM) fully consumed before next tile
    }
}

// ---------------- BN stats reduce -> affine a,c per column ----------------
__global__ __launch_bounds__(128)
void k_colreduce2(const float* __restrict__ bn_g, const float* __restrict__ bn_b) {
    int d = blockIdx.x;                   // column
    int t = threadIdx.x;
    __shared__ float ss[128], qq[128];
    float s = 0.f, q = 0.f;
    for (int c = t; c < MTILES; c += 128) {
        s += g_partial2[(size_t)c * 2 * DD + d];
        q += g_partial2[(size_t)c * 2 * DD + DD + d];
    }
    ss[t] = s; qq[t] = q;
    __syncthreads();
    for (int o = 64; o > 0; o >>= 1) {
        if (t < o) { ss[t] += ss[t + o]; qq[t] += qq[t + o]; }
        __syncthreads();
    }
    if (t == 0) {
        float mu = ss[0] / (float)NN;
        float var = qq[0] / (float)NN - mu * mu;
        float rstd = rsqrtf(var + BN_EPS);
        float a = rstd * bn_g[d];
        g_stats[d] = a;
        g_stats[DD + d] = bn_b[d] - mu * a;
    }
}

// ---------------- pooling with fused final-layer BN+ReLU ----------------
__device__ __forceinline__ int lower_bound_dev(const int* a, int n, int key) {
    int lo = 0, hi = n;
    while (lo < hi) {
        int mid = (lo + hi) >> 1;
        if (a[mid] < key) lo = mid + 1; else hi = mid;
    }
    return lo;
}

__global__ void k_pool_bn(const int* __restrict__ batch) {
    int b = blockIdx.x;
    int d = threadIdx.x;
    __shared__ int lo_s, hi_s;
    if (d == 0) {
        lo_s = lower_bound_dev(batch, NN, b);
        hi_s = lower_bound_dev(batch, NN, b + 1);
    }
    __syncthreads();
    int lo = lo_s, hi = hi_s;
    const float a = g_stats[d];
    const float c = g_stats[DD + d];
    float s = 0.f;
    for (int i = lo; i < hi; i++) {
        float z = __half2float(g_zh[(size_t)i * DD + d]);
        s += fmaxf(z * a + c, 0.f);
    }
    float cnt = (float)(hi - lo);
    g_pooled[b * DD + d] = s / fmaxf(cnt, 1.f);
}

// ---------------- output MLP ----------------
__global__ void k_out(const float* __restrict__ Wo1, const float* __restrict__ bo1,
                      const float* __restrict__ Wo2, const float* __restrict__ bo2,
                      float* __restrict__ out) {
    int b = blockIdx.x;
    int j = threadIdx.x;
    __shared__ float p[DD];
    __shared__ float r0[128], r1[128];
    p[j] = g_pooled[b * DD + j];
    p[j + 128] = g_pooled[b * DD + 128 + j];
    __syncthreads();
    float acc = bo1[j];
    for (int k = 0; k < DD; k++) acc += p[k] * Wo1[k * 128 + j];
    float hv = (acc > 20.f) ? acc : log1pf(expf(acc));
    r0[j] = hv * Wo2[j * 2 + 0];
    r1[j] = hv * Wo2[j * 2 + 1];
    __syncthreads();
    for (int s = 64; s > 0; s >>= 1) {
        if (j < s) { r0[j] += r0[j + s]; r1[j] += r1[j + s]; }
        __syncthreads();
    }
    if (j == 0) {
        out[b * 2 + 0] = r0[0] + bo2[0];
        out[b * 2 + 1] = r1[0] + bo2[1];
    }
}

// ---------------- launch ----------------
extern "C" void kernel_launch(void* const* d_in, const int* in_sizes, int n_in,
                              void* d_out, int out_size) {
    const int*   x          = (const int*)d_in[0];
    const int*   edge_index = (const int*)d_in[1];
    const int*   edge_attr  = (const int*)d_in[2];
    const int*   batch      = (const int*)d_in[3];
    const float* x_emb1     = (const float*)d_in[4];
    const float* x_emb2     = (const float*)d_in[5];
    const float* edge_emb1  = (const float*)d_in[6];
    const float* edge_emb2  = (const float*)d_in[7];
    const float* W1         = (const float*)d_in[8];
    const float* b1         = (const float*)d_in[9];
    const float* W2         = (const float*)d_in[10];
    const float* b2         = (const float*)d_in[11];  // dropped (BN-invariant)
    const float* bn_g       = (const float*)d_in[12];
    const float* bn_b       = (const float*)d_in[13];
    const float* Wo1        = (const float*)d_in[14];
    const float* bo1        = (const float*)d_in[15];
    const float* Wo2        = (const float*)d_in[16];
    const float* bo2        = (const float*)d_in[17];
    float* out = (float*)d_out;
    (void)b2;

    cudaFuncSetAttribute(gemm_wmma<0>, cudaFuncAttributeMaxDynamicSharedMemorySize, GEMM_SMEM);
    cudaFuncSetAttribute(gemm_wmma<1>, cudaFuncAttributeMaxDynamicSharedMemorySize, GEMM_SMEM);

    // CSR build (cursor fused into scan; packed records scattered directly)
    k_zero_deg<<<(NN + 255) / 256, 256>>>();
    k_hist<<<(EE + 255) / 256, 256>>>(edge_index);
    k_scan<<<1, 1024>>>();
    k_scatter<<<(EE + 255) / 256, 256>>>(edge_index, edge_attr);
    k_sortseg<<<(NN + 255) / 256, 256>>>();

    // weight transpose -> half
    k_prep_w1h<<<(LL * HID * DD + 255) / 256, 256>>>(W1);
    k_prep_w2h<<<(LL * DD * HID + 255) / 256, 256>>>(W2);

    k_init_h<<<NN, DD>>>(x, x_emb1, x_emb2);

    for (int l = 0; l < LL; l++) {
        const float* e1 = edge_emb1 + (size_t)l * 5 * DD;
        const float* e2 = edge_emb2 + (size_t)l * 3 * DD;
        if (l == 0)
            k_agg<0><<<(NN + AGG_NPB - 1) / AGG_NPB, 128>>>(e1, e2);
        else
            k_agg<1><<<(NN + AGG_NPB - 1) / AGG_NPB, 128>>>(e1, e2);
        // GEMM1: t1h = half(relu(aggh @ W1 + b1))   [persistent tiles]
        gemm_wmma<0><<<PERSIST_GRID, 256, GEMM_SMEM>>>(b1 + (size_t)l * HID, l);
        // GEMM2: zh = half(t1h @ W2) + fused BN column partials [persistent tiles]
        gemm_wmma<1><<<PERSIST_GRID, 256, GEMM_SMEM>>>(b1 + (size_t)l * HID, l);
        k_colreduce2<<<DD, 128>>>(bn_g + (size_t)l * DD, bn_b + (size_t)l * DD);
    }

    k_pool_bn<<<BB, DD>>>(batch);
    k_out<<<BB, 128>>>(Wo1, bo1, Wo2, bo2, out);
}

// round 16
// speedup vs baseline: 1.0675x; 1.0675x over previous
#include <cuda_runtime.h>
#include <cuda_fp16.h>
#include <mma.h>
#include <math.h>
#include <stdint.h>

using namespace nvcuda;

// Problem constants
#define NN 100000
#define NNP 100096          // padded to multiple of 128 for unguarded tile stores
#define EE 200000
#define BB 2048
#define DD 256
#define LL 5
#define HID 512
#define BN_EPS 1e-5f
#define AGG_NPB 8
#define MTILES (NNP / 128)  // 782
#define SCAN_NBLK ((NN + 255) / 256)   // 391

// ---------------- scratch (device globals; no allocation allowed) ------------
__device__ __half g_hh[(size_t)NNP * DD];          // layer-0 node features (half)
__device__ __half g_zh[(size_t)NNP * DD];          // z (GEMM2 out, half)
__device__ __half g_aggh[(size_t)NNP * DD];        // GEMM1 input (half)
__device__ __half g_t1h[(size_t)NNP * HID];        // GEMM2 input (half)
__device__ __half g_w1h[(size_t)LL * HID * DD];    // [l][n][k] = W1[l][k][n]
__device__ __half g_w2h[(size_t)LL * DD * HID];    // [l][n][k] = W2[l][k][n]
__device__ int    g_deg[NN];
__device__ int    g_rowptr[NN + 1];
__device__ int    g_cursor[NN];
__device__ int    g_bsum[SCAN_NBLK];
__device__ int    g_epack[EE];                     // src<<4 | (bt*3+bd), sorted per segment
__device__ float  g_partial2[(size_t)MTILES * 2 * DD];
__device__ float  g_stats[2 * DD];                 // [0:256)=a, [256:512)=c
__device__ float  g_pooled[BB * DD];

static __device__ __forceinline__ uint32_t smem_u32(const void* p) {
    uint32_t a;
    asm("{ .reg .u64 t; cvta.to.shared.u64 t, %1; cvt.u32.u64 %0, t; }" : "=r"(a) : "l"(p));
    return a;
}
static __device__ __forceinline__ void cp16(uint32_t dst, const void* src) {
    asm volatile("cp.async.cg.shared.global [%0], [%1], 16;" :: "r"(dst), "l"(src));
}
#define CP_COMMIT() asm volatile("cp.async.commit_group;" ::: "memory")
#define CP_WAIT(n)  asm volatile("cp.async.wait_group %0;" :: "n"(n) : "memory")

// ---------------- CSR build ----------------
__global__ void k_zero_deg() {
    int i = blockIdx.x * blockDim.x + threadIdx.x;
    if (i < NN) g_deg[i] = 0;
}

__global__ void k_hist(const int* __restrict__ edge_index) {
    int e = blockIdx.x * blockDim.x + threadIdx.x;
    if (e < EE) atomicAdd(&g_deg[edge_index[EE + e]], 1);
}

// parallel scan phase 1: per-block inclusive scan of deg; block sums out
__global__ __launch_bounds__(256)
void k_scan1() {
    __shared__ int s[256];
    int blk = blockIdx.x, tid = threadIdx.x;
    int i = blk * 256 + tid;
    int v = (i < NN) ? g_deg[i] : 0;
    s[tid] = v;
    __syncthreads();
    for (int off = 1; off < 256; off <<= 1) {
        int t = (tid >= off) ? s[tid - off] : 0;
        __syncthreads();
        s[tid] += t;
        __syncthreads();
    }
    if (i < NN) g_rowptr[i + 1] = s[tid];   // local inclusive, offset later
    if (tid == 255) g_bsum[blk] = s[255];
}

// phase 2: exclusive scan of block sums (single block)
__global__ __launch_bounds__(512)
void k_scan2() {
    __shared__ int s[512];
    int tid = threadIdx.x;
    int v = (tid < SCAN_NBLK) ? g_bsum[tid] : 0;
    s[tid] = v;
    __syncthreads();
    for (int off = 1; off < 512; off <<= 1) {
        int t = (tid >= off) ? s[tid - off] : 0;
        __syncthreads();
        s[tid] += t;
        __syncthreads();
    }
    if (tid < SCAN_NBLK) g_bsum[tid] = s[tid] - v;   // exclusive
}

// phase 3: add block offsets; derive cursor; rowptr[0]=0
__global__ __launch_bounds__(256)
void k_scan3() {
    int i = blockIdx.x * 256 + threadIdx.x;
    if (i < NN) {
        int inc = g_rowptr[i + 1] + g_bsum[blockIdx.x];
        g_rowptr[i + 1] = inc;
        g_cursor[i] = inc - g_deg[i];
    }
    if (i == 0) g_rowptr[0] = 0;
}

// scatter packed records directly (order nondeterministic; fixed by value sort)
__global__ void k_scatter(const int* __restrict__ edge_index,
                          const int* __restrict__ edge_attr) {
    int e = blockIdx.x * blockDim.x + threadIdx.x;
    if (e < EE) {
        int dstn = edge_index[EE + e];
        int sn = edge_index[e];
        int bt = edge_attr[e * 2 + 0];
        int bd = edge_attr[e * 2 + 1];
        int pos = atomicAdd(&g_cursor[dstn], 1);
        g_epack[pos] = (sn << 4) | (bt * 3 + bd);
    }
}

// deterministic order: sort packed values within each segment
__global__ void k_sortseg() {
    int i = blockIdx.x * blockDim.x + threadIdx.x;
    if (i >= NN) return;
    int s = g_rowptr[i], e = g_rowptr[i + 1];
    for (int a = s + 1; a < e; a++) {
        int v = g_epack[a];
        int b = a - 1;
        while (b >= s && g_epack[b] > v) { g_epack[b + 1] = g_epack[b]; b--; }
        g_epack[b + 1] = v;
    }
}

// ---------------- weight transpose -> half ----------------
__global__ void k_prep_w1h(const float* __restrict__ W1) {
    int idx = blockIdx.x * blockDim.x + threadIdx.x;
    if (idx >= LL * HID * DD) return;
    int l = idx / (HID * DD);
    int rem = idx - l * (HID * DD);
    int n = rem / DD;
    int k = rem - n * DD;
    g_w1h[idx] = __float2half_rn(W1[(size_t)l * DD * HID + (size_t)k * HID + n]);
}

__global__ void k_prep_w2h(const float* __restrict__ W2) {
    int idx = blockIdx.x * blockDim.x + threadIdx.x;
    if (idx >= LL * DD * HID) return;
    int l = idx / (DD * HID);
    int rem = idx - l * (DD * HID);
    int n = rem / HID;
    int k = rem - n * HID;
    g_w2h[idx] = __float2half_rn(W2[(size_t)l * HID * DD + (size_t)k * DD + n]);
}

// ---------------- h init (half) ----------------
__global__ void k_init_h(const int* __restrict__ x,
                         const float* __restrict__ emb1,
                         const float* __restrict__ emb2) {
    int i = blockIdx.x;
    int d = threadIdx.x;
    int a = x[i * 2 + 0], c = x[i * 2 + 1];
    g_hh[(size_t)i * DD + d] = __float2half_rn(emb1[a * DD + d] + emb2[c * DD + d]);
}

// ---------------- aggregation: half2, packed edges, optional fused BN -------
// BN==0: reads g_hh raw (layer 0). BN==1: reads g_zh, applies relu(z*a+c).
template<int BN>
__global__ __launch_bounds__(128)
void k_agg(const float* __restrict__ e1, const float* __restrict__ e2) {
    int base = blockIdx.x * AGG_NPB;
    int d2 = threadIdx.x;                 // 0..127 -> features 2*d2, 2*d2+1
    __shared__ float sc[15][DD];          // combined e1[bt]+e2[bd]
    for (int idx = d2; idx < 15 * DD; idx += 128) {
        int c = idx >> 8;                 // 0..14
        int dd = idx & (DD - 1);
        sc[c][dd] = e1[(c / 3) * DD + dd] + e2[(c % 3) * DD + dd];
    }
    __syncthreads();

    const __half2* H2 = BN ? (const __half2*)g_zh : (const __half2*)g_hh;
    __half2* A2 = (__half2*)g_aggh;
    const float2 selfc = *(const float2*)&sc[12][2 * d2];   // bt=4, bd=0

    float2 bna = make_float2(0.f, 0.f), bnc = make_float2(0.f, 0.f);
    if (BN) {
        bna = *(const float2*)&g_stats[2 * d2];
        bnc = *(const float2*)&g_stats[DD + 2 * d2];
    }

    auto loadh = [&](size_t idx) -> float2 {
        __half2 hv = H2[idx];
        float2 v;
        v.x = __low2float(hv);
        v.y = __high2float(hv);
        if (BN) {
            v.x = fmaxf(v.x * bna.x + bnc.x, 0.f);
            v.y = fmaxf(v.y * bna.y + bnc.y, 0.f);
        }
        return v;
    };

#pragma unroll
    for (int j = 0; j < AGG_NPB; j++) {
        int i = base + j;
        if (i >= NN) break;
        float2 hv = loadh((size_t)i * 128 + d2);
        float2 acc;
        acc.x = hv.x + selfc.x;
        acc.y = hv.y + selfc.y;
        int s = g_rowptr[i], e = g_rowptr[i + 1];
        for (int p = s; p < e; p++) {
            int pk = g_epack[p];
            int sn = pk >> 4;
            int c = pk & 15;
            float2 nh = loadh((size_t)sn * 128 + d2);
            float2 scv = *(const float2*)&sc[c][2 * d2];
            acc.x += nh.x + scv.x;
            acc.y += nh.y + scv.y;
        }
        A2[(size_t)i * 128 + d2] = __floats2half2_rn(acc.x, acc.y);
    }
}

// =================== wmma fp16 GEMM, 2-stage cp.async, BK=32 ================
// (R11 proven-best configuration, byte-identical mainloop)
// BM=128, BN=128, BK=32. 8 warps = 2(M) x 4(N); warp tile 64x32 = 4x2 wmma tiles.
// G==0: g_t1h = half(relu(g_aggh @ W1h + b1))
// G==1: g_zh = half(g_t1h @ W2h)  + fused column sum/sumsq partials (fp32)
#define HLD 40                             // halfs per SMEM row (32 + pad 8) = 80B
#define STG_HALFS (2 * 128 * HLD)          // A + B per stage = 10240 halfs
#define GEMM_SMEM (2 * STG_HALFS * 2)      // 40960 bytes (double buffered)
#define ELD 68                             // epilogue float tile leading dim

template<int G>
__global__ __launch_bounds__(256, 2)
void gemm_wmma(const float* __restrict__ bias, int l) {
    constexpr int K  = (G == 0) ? DD : HID;
    constexpr int NC = (G == 0) ? HID : DD;
    constexpr int NIT = K / 32;

    const __half* __restrict__ A = (G == 0) ? (const __half*)g_aggh : (const __half*)g_t1h;
    const __half* __restrict__ BT =
        ((G == 0) ? (const __half*)g_w1h : (const __half*)g_w2h) + (size_t)l * K * NC;

    extern __shared__ __half smh[];
    __shared__ float ps[4][64];
    __shared__ float pq[4][64];

    const int tid = threadIdx.x;
    const int wid = tid >> 5;
    const int warpM = wid & 1;    // 0..1  (64 rows)
    const int warpN = wid >> 1;   // 0..3  (32 cols)
    const int m0 = blockIdx.y * 128;
    const int n0 = blockIdx.x * 128;

    // staging: thread t -> row = t>>1 (0..127), 32B segment = (t&1)
    const int row = tid >> 1;
    const int seg = tid & 1;

    const uint32_t smBase = smem_u32(smh);
    const uint32_t smA[2] = { smBase + (uint32_t)(row * HLD + seg * 16) * 2u,
                              smBase + (uint32_t)(STG_HALFS + row * HLD + seg * 16) * 2u };
    const uint32_t smB[2] = { smA[0] + 128u * HLD * 2u, smA[1] + 128u * HLD * 2u };
    const __half* gA = A  + (size_t)(m0 + row) * K + seg * 16;
    const __half* gB = BT + (size_t)(n0 + row) * K + seg * 16;

    auto issue_stage = [&](int it, int buf) {
        const __half* a = gA + it * 32;
        const __half* b = gB + it * 32;
        cp16(smA[buf],       a);
        cp16(smA[buf] + 16u, a + 8);
        cp16(smB[buf],       b);
        cp16(smB[buf] + 16u, b + 8);
        CP_COMMIT();
    };

    wmma::fragment<wmma::accumulator, 16, 16, 16, float> acc[4][2];
#pragma unroll
    for (int t = 0; t < 4; t++)
#pragma unroll
        for (int u = 0; u < 2; u++) wmma::fill_fragment(acc[t][u], 0.0f);

    issue_stage(0, 0);
    issue_stage(1, 1);

    for (int it = 0; it < NIT; it++) {
        int buf = it & 1;
        if (it == NIT - 1) CP_WAIT(0); else CP_WAIT(1);
        __syncthreads();

        const __half* As = smh + buf * STG_HALFS;
        const __half* Bs = As + 128 * HLD;
#pragma unroll
        for (int ks = 0; ks < 2; ks++) {
            wmma::fragment<wmma::matrix_a, 16, 16, 16, __half, wmma::row_major> af[4];
            wmma::fragment<wmma::matrix_b, 16, 16, 16, __half, wmma::col_major> bf[2];
#pragma unroll
            for (int t = 0; t < 4; t++)
                wmma::load_matrix_sync(af[t], As + (warpM * 64 + t * 16) * HLD + ks * 16, HLD);
#pragma unroll
            for (int u = 0; u < 2; u++)
                wmma::load_matrix_sync(bf[u], Bs + (warpN * 32 + u * 16) * HLD + ks * 16, HLD);
#pragma unroll
            for (int t = 0; t < 4; t++)
#pragma unroll
                for (int u = 0; u < 2; u++)
                    wmma::mma_sync(acc[t][u], af[t], bf[u], acc[t][u]);
        }

        if (it + 2 < NIT) {
            __syncthreads();              // all warps done reading buf before refill
            issue_stage(it + 2, buf);
        }
    }

    // -------- epilogue: 2 passes of 64 columns via SMEM float tile ----------
    float* ep = (float*)smh;              // 128 x ELD floats = 34816 B <= GEMM_SMEM
    const int coff = seg * 32;
#pragma unroll
    for (int p = 0; p < 2; p++) {
        __syncthreads();
        if ((warpN >> 1) == p) {
#pragma unroll
            for (int t = 0; t < 4; t++)
#pragma unroll
                for (int u = 0; u < 2; u++)
                    wmma::store_matrix_sync(
                        ep + (warpM * 64 + t * 16) * ELD + (warpN & 1) * 32 + u * 16,
                        acc[t][u], ELD, wmma::mem_row_major);
        }
        __syncthreads();

        if (G == 0) {
            const float* srow = ep + row * ELD + coff;
            const float* brow = bias + n0 + p * 64 + coff;
            __half2* crow = (__half2*)(g_t1h + (size_t)(m0 + row) * NC + n0 + p * 64 + coff);
#pragma unroll
            for (int i = 0; i < 16; i++) {
                float2 v = *(const float2*)(srow + 2 * i);
                float2 bp = *(const float2*)(brow + 2 * i);
                crow[i] = __floats2half2_rn(fmaxf(v.x + bp.x, 0.f), fmaxf(v.y + bp.y, 0.f));
            }
        } else {
            // half store of z to g_zh
            const float* srow = ep + row * ELD + coff;
            __half2* crow = (__half2*)(g_zh + (size_t)(m0 + row) * NC + n0 + p * 64 + coff);
#pragma unroll
            for (int i = 0; i < 16; i++) {
                float2 v = *(const float2*)(srow + 2 * i);
                crow[i] = __floats2half2_rn(v.x, v.y);
            }

            // fused column partials from exact fp32 tile (exclude padding rows)
            const int col = tid & 63;
            const int grp = tid >> 6;
            const int rlim = (NN - m0 < 128) ? (NN - m0) : 128;
            float s = 0.f, q = 0.f;
            for (int r = grp * 32; r < grp * 32 + 32; r++) {
                if (r >= rlim) break;
                float v = ep[r * ELD + col];
                s += v; q += v * v;
            }
            ps[grp][col] = s;
            pq[grp][col] = q;
            __syncthreads();
            if (grp == 0) {
                float S = ps[0][col] + ps[1][col] + ps[2][col] + ps[3][col];
                float Q = pq[0][col] + pq[1][col] + pq[2][col] + pq[3][col];
                int cg = n0 + p * 64 + col;
                g_partial2[(size_t)blockIdx.y * 2 * DD + cg] = S;
                g_partial2[(size_t)blockIdx.y * 2 * DD + DD + cg] = Q;
            }
        }
    }
}

// ---------------- BN stats reduce -> affine a,c per column ----------------
__global__ __launch_bounds__(128)
void k_colreduce2(const float* __restrict__ bn_g, const float* __restrict__ bn_b) {
    int d = blockIdx.x;                   // column
    int t = threadIdx.x;
    __shared__ float ss[128], qq[128];
    float s = 0.f, q = 0.f;
    for (int c = t; c < MTILES; c += 128) {
        s += g_partial2[(size_t)c * 2 * DD + d];
        q += g_partial2[(size_t)c * 2 * DD + DD + d];
    }
    ss[t] = s; qq[t] = q;
    __syncthreads();
    for (int o = 64; o > 0; o >>= 1) {
        if (t < o) { ss[t] += ss[t + o]; qq[t] += qq[t + o]; }
        __syncthreads();
    }
    if (t == 0) {
        float mu = ss[0] / (float)NN;
        float var = qq[0] / (float)NN - mu * mu;
        float rstd = rsqrtf(var + BN_EPS);
        float a = rstd * bn_g[d];
        g_stats[d] = a;
        g_stats[DD + d] = bn_b[d] - mu * a;
    }
}

// ---------------- pooling with fused final-layer BN+ReLU ----------------
__device__ __forceinline__ int lower_bound_dev(const int* a, int n, int key) {
    int lo = 0, hi = n;
    while (lo < hi) {
        int mid = (lo + hi) >> 1;
        if (a[mid] < key) lo = mid + 1; else hi = mid;
    }
    return lo;
}

__global__ void k_pool_bn(const int* __restrict__ batch) {
    int b = blockIdx.x;
    int d = threadIdx.x;
    __shared__ int lo_s, hi_s;
    if (d == 0) {
        lo_s = lower_bound_dev(batch, NN, b);
        hi_s = lower_bound_dev(batch, NN, b + 1);
    }
    __syncthreads();
    int lo = lo_s, hi = hi_s;
    const float a = g_stats[d];
    const float c = g_stats[DD + d];
    float s = 0.f;
    for (int i = lo; i < hi; i++) {
        float z = __half2float(g_zh[(size_t)i * DD + d]);
        s += fmaxf(z * a + c, 0.f);
    }
    float cnt = (float)(hi - lo);
    g_pooled[b * DD + d] = s / fmaxf(cnt, 1.f);
}

// ---------------- output MLP ----------------
__global__ void k_out(const float* __restrict__ Wo1, const float* __restrict__ bo1,
                      const float* __restrict__ Wo2, const float* __restrict__ bo2,
                      float* __restrict__ out) {
    int b = blockIdx.x;
    int j = threadIdx.x;
    __shared__ float p[DD];
    __shared__ float r0[128], r1[128];
    p[j] = g_pooled[b * DD + j];
    p[j + 128] = g_pooled[b * DD + 128 + j];
    __syncthreads();
    float acc = bo1[j];
    for (int k = 0; k < DD; k++) acc += p[k] * Wo1[k * 128 + j];
    float hv = (acc > 20.f) ? acc : log1pf(expf(acc));
    r0[j] = hv * Wo2[j * 2 + 0];
    r1[j] = hv * Wo2[j * 2 + 1];
    __syncthreads();
    for (int s = 64; s > 0; s >>= 1) {
        if (j < s) { r0[j] += r0[j + s]; r1[j] += r1[j + s]; }
        __syncthreads();
    }
    if (j == 0) {
        out[b * 2 + 0] = r0[0] + bo2[0];
        out[b * 2 + 1] = r1[0] + bo2[1];
    }
}

// ---------------- launch ----------------
extern "C" void kernel_launch(void* const* d_in, const int* in_sizes, int n_in,
                              void* d_out, int out_size) {
    const int*   x          = (const int*)d_in[0];
    const int*   edge_index = (const int*)d_in[1];
    const int*   edge_attr  = (const int*)d_in[2];
    const int*   batch      = (const int*)d_in[3];
    const float* x_emb1     = (const float*)d_in[4];
    const float* x_emb2     = (const float*)d_in[5];
    const float* edge_emb1  = (const float*)d_in[6];
    const float* edge_emb2  = (const float*)d_in[7];
    const float* W1         = (const float*)d_in[8];
    const float* b1         = (const float*)d_in[9];
    const float* W2         = (const float*)d_in[10];
    const float* b2         = (const float*)d_in[11];  // dropped (BN-invariant)
    const float* bn_g       = (const float*)d_in[12];
    const float* bn_b       = (const float*)d_in[13];
    const float* Wo1        = (const float*)d_in[14];
    const float* bo1        = (const float*)d_in[15];
    const float* Wo2        = (const float*)d_in[16];
    const float* bo2        = (const float*)d_in[17];
    float* out = (float*)d_out;
    (void)b2;

    cudaFuncSetAttribute(gemm_wmma<0>, cudaFuncAttributeMaxDynamicSharedMemorySize, GEMM_SMEM);
    cudaFuncSetAttribute(gemm_wmma<1>, cudaFuncAttributeMaxDynamicSharedMemorySize, GEMM_SMEM);

    // CSR build (parallel scan; packed records scattered directly)
    k_zero_deg<<<(NN + 255) / 256, 256>>>();
    k_hist<<<(EE + 255) / 256, 256>>>(edge_index);
    k_scan1<<<SCAN_NBLK, 256>>>();
    k_scan2<<<1, 512>>>();
    k_scan3<<<SCAN_NBLK, 256>>>();
    k_scatter<<<(EE + 255) / 256, 256>>>(edge_index, edge_attr);
    k_sortseg<<<(NN + 255) / 256, 256>>>();

    // weight transpose -> half
    k_prep_w1h<<<(LL * HID * DD + 255) / 256, 256>>>(W1);
    k_prep_w2h<<<(LL * DD * HID + 255) / 256, 256>>>(W2);

    k_init_h<<<NN, DD>>>(x, x_emb1, x_emb2);

    for (int l = 0; l < LL; l++) {
        const float* e1 = edge_emb1 + (size_t)l * 5 * DD;
        const float* e2 = edge_emb2 + (size_t)l * 3 * DD;
        if (l == 0)
            k_agg<0><<<(NN + AGG_NPB - 1) / AGG_NPB, 128>>>(e1, e2);
        else
            k_agg<1><<<(NN + AGG_NPB - 1) / AGG_NPB, 128>>>(e1, e2);
        {   // GEMM1: t1h = half(relu(aggh @ W1 + b1))
            dim3 grid(HID / 128, MTILES);
            gemm_wmma<0><<<grid, 256, GEMM_SMEM>>>(b1 + (size_t)l * HID, l);
        }
        {   // GEMM2: zh = half(t1h @ W2) + fused BN column partials
            dim3 grid(DD / 128, MTILES);
            gemm_wmma<1><<<grid, 256, GEMM_SMEM>>>(b1 + (size_t)l * HID, l);
        }
        k_colreduce2<<<DD, 128>>>(bn_g + (size_t)l * DD, bn_b + (size_t)l * DD);
    }

    k_pool_bn<<<BB, DD>>>(batch);
    k_out<<<BB, 128>>>(Wo1, bo1, Wo2, bo2, out);
}

// round 17
// speedup vs baseline: 1.0952x; 1.0260x over previous
#include <cuda_runtime.h>
#include <cuda_fp16.h>
#include <mma.h>
#include <math.h>
#include <stdint.h>

using namespace nvcuda;

// Problem constants
#define NN 100000
#define NNP 100096          // padded to multiple of 128 for unguarded tile stores
#define EE 200000
#define BB 2048
#define DD 256
#define LL 5
#define HID 512
#define BN_EPS 1e-5f
#define AGG_NPB 16
#define MTILES (NNP / 128)  // 782
#define SCAN_NBLK ((NN + 255) / 256)   // 391

// ---------------- scratch (device globals; no allocation allowed) ------------
__device__ __half g_hh[(size_t)NNP * DD];          // layer-0 node features (half)
__device__ __half g_zh[(size_t)NNP * DD];          // z (GEMM2 out, half)
__device__ __half g_aggh[(size_t)NNP * DD];        // GEMM1 input (half)
__device__ __half g_t1h[(size_t)NNP * HID];        // GEMM2 input (half)
__device__ __half g_w1h[(size_t)LL * HID * DD];    // [l][n][k] = W1[l][k][n]
__device__ __half g_w2h[(size_t)LL * DD * HID];    // [l][n][k] = W2[l][k][n]
__device__ int    g_deg[NN];
__device__ int    g_rowptr[NN + 1];
__device__ int    g_cursor[NN];
__device__ int    g_bsum[SCAN_NBLK];
__device__ int    g_epack[EE];                     // src<<4 | (bt*3+bd), sorted per segment
__device__ float  g_partial2[(size_t)MTILES * 2 * DD];
__device__ float  g_stats[2 * DD];                 // [0:256)=a, [256:512)=c
__device__ float  g_pooled[BB * DD];

static __device__ __forceinline__ uint32_t smem_u32(const void* p) {
    uint32_t a;
    asm("{ .reg .u64 t; cvta.to.shared.u64 t, %1; cvt.u32.u64 %0, t; }" : "=r"(a) : "l"(p));
    return a;
}
static __device__ __forceinline__ void cp16(uint32_t dst, const void* src) {
    asm volatile("cp.async.cg.shared.global [%0], [%1], 16;" :: "r"(dst), "l"(src));
}
#define CP_COMMIT() asm volatile("cp.async.commit_group;" ::: "memory")
#define CP_WAIT(n)  asm volatile("cp.async.wait_group %0;" :: "n"(n) : "memory")

// ---------------- CSR build ----------------
__global__ void k_zero_deg() {
    int i = blockIdx.x * blockDim.x + threadIdx.x;
    if (i < NN) g_deg[i] = 0;
}

__global__ void k_hist(const int* __restrict__ edge_index) {
    int e = blockIdx.x * blockDim.x + threadIdx.x;
    if (e < EE) atomicAdd(&g_deg[edge_index[EE + e]], 1);
}

// parallel scan phase 1: per-block inclusive scan of deg; block sums out
__global__ __launch_bounds__(256)
void k_scan1() {
    __shared__ int s[256];
    int blk = blockIdx.x, tid = threadIdx.x;
    int i = blk * 256 + tid;
    int v = (i < NN) ? g_deg[i] : 0;
    s[tid] = v;
    __syncthreads();
    for (int off = 1; off < 256; off <<= 1) {
        int t = (tid >= off) ? s[tid - off] : 0;
        __syncthreads();
        s[tid] += t;
        __syncthreads();
    }
    if (i < NN) g_rowptr[i + 1] = s[tid];   // local inclusive, offset later
    if (tid == 255) g_bsum[blk] = s[255];
}

// phase 2: exclusive scan of block sums (single block)
__global__ __launch_bounds__(512)
void k_scan2() {
    __shared__ int s[512];
    int tid = threadIdx.x;
    int v = (tid < SCAN_NBLK) ? g_bsum[tid] : 0;
    s[tid] = v;
    __syncthreads();
    for (int off = 1; off < 512; off <<= 1) {
        int t = (tid >= off) ? s[tid - off] : 0;
        __syncthreads();
        s[tid] += t;
        __syncthreads();
    }
    if (tid < SCAN_NBLK) g_bsum[tid] = s[tid] - v;   // exclusive
}

// phase 3: add block offsets; derive cursor; rowptr[0]=0
__global__ __launch_bounds__(256)
void k_scan3() {
    int i = blockIdx.x * 256 + threadIdx.x;
    if (i < NN) {
        int inc = g_rowptr[i + 1] + g_bsum[blockIdx.x];
        g_rowptr[i + 1] = inc;
        g_cursor[i] = inc - g_deg[i];
    }
    if (i == 0) g_rowptr[0] = 0;
}

// scatter packed records directly (order nondeterministic; fixed by value sort)
__global__ void k_scatter(const int* __restrict__ edge_index,
                          const int* __restrict__ edge_attr) {
    int e = blockIdx.x * blockDim.x + threadIdx.x;
    if (e < EE) {
        int dstn = edge_index[EE + e];
        int sn = edge_index[e];
        int bt = edge_attr[e * 2 + 0];
        int bd = edge_attr[e * 2 + 1];
        int pos = atomicAdd(&g_cursor[dstn], 1);
        g_epack[pos] = (sn << 4) | (bt * 3 + bd);
    }
}

// deterministic order: sort packed values within each segment
__global__ void k_sortseg() {
    int i = blockIdx.x * blockDim.x + threadIdx.x;
    if (i >= NN) return;
    int s = g_rowptr[i], e = g_rowptr[i + 1];
    for (int a = s + 1; a < e; a++) {
        int v = g_epack[a];
        int b = a - 1;
        while (b >= s && g_epack[b] > v) { g_epack[b + 1] = g_epack[b]; b--; }
        g_epack[b + 1] = v;
    }
}

// ---------------- weight transpose -> half (both W1 and W2 in one kernel) ---
#define W1_ELEMS (LL * HID * DD)
#define W2_ELEMS (LL * DD * HID)
__global__ void k_prep_w(const float* __restrict__ W1, const float* __restrict__ W2) {
    int idx = blockIdx.x * blockDim.x + threadIdx.x;
    if (idx < W1_ELEMS) {
        int l = idx / (HID * DD);
        int rem = idx - l * (HID * DD);
        int n = rem / DD;
        int k = rem - n * DD;
        g_w1h[idx] = __float2half_rn(W1[(size_t)l * DD * HID + (size_t)k * HID + n]);
    } else if (idx < W1_ELEMS + W2_ELEMS) {
        int j = idx - W1_ELEMS;
        int l = j / (DD * HID);
        int rem = j - l * (DD * HID);
        int n = rem / HID;
        int k = rem - n * HID;
        g_w2h[j] = __float2half_rn(W2[(size_t)l * HID * DD + (size_t)k * DD + n]);
    }
}

// ---------------- h init (half) ----------------
__global__ void k_init_h(const int* __restrict__ x,
                         const float* __restrict__ emb1,
                         const float* __restrict__ emb2) {
    int i = blockIdx.x;
    int d = threadIdx.x;
    int a = x[i * 2 + 0], c = x[i * 2 + 1];
    g_hh[(size_t)i * DD + d] = __float2half_rn(emb1[a * DD + d] + emb2[c * DD + d]);
}

// ---------------- aggregation: half2, packed edges, optional fused BN -------
// BN==0: reads g_hh raw (layer 0). BN==1: reads g_zh, applies relu(z*a+c).
template<int BN>
__global__ __launch_bounds__(128)
void k_agg(const float* __restrict__ e1, const float* __restrict__ e2) {
    int base = blockIdx.x * AGG_NPB;
    int d2 = threadIdx.x;                 // 0..127 -> features 2*d2, 2*d2+1
    __shared__ float sc[15][DD];          // combined e1[bt]+e2[bd]
    for (int idx = d2; idx < 15 * DD; idx += 128) {
        int c = idx >> 8;                 // 0..14
        int dd = idx & (DD - 1);
        sc[c][dd] = e1[(c / 3) * DD + dd] + e2[(c % 3) * DD + dd];
    }
    __syncthreads();

    const __half2* H2 = BN ? (const __half2*)g_zh : (const __half2*)g_hh;
    __half2* A2 = (__half2*)g_aggh;
    const float2 selfc = *(const float2*)&sc[12][2 * d2];   // bt=4, bd=0

    float2 bna = make_float2(0.f, 0.f), bnc = make_float2(0.f, 0.f);
    if (BN) {
        bna = *(const float2*)&g_stats[2 * d2];
        bnc = *(const float2*)&g_stats[DD + 2 * d2];
    }

    auto loadh = [&](size_t idx) -> float2 {
        __half2 hv = H2[idx];
        float2 v;
        v.x = __low2float(hv);
        v.y = __high2float(hv);
        if (BN) {
            v.x = fmaxf(v.x * bna.x + bnc.x, 0.f);
            v.y = fmaxf(v.y * bna.y + bnc.y, 0.f);
        }
        return v;
    };

#pragma unroll
    for (int j = 0; j < AGG_NPB; j++) {
        int i = base + j;
        if (i >= NN) break;
        float2 hv = loadh((size_t)i * 128 + d2);
        float2 acc;
        acc.x = hv.x + selfc.x;
        acc.y = hv.y + selfc.y;
        int s = g_rowptr[i], e = g_rowptr[i + 1];
        for (int p = s; p < e; p++) {
            int pk = g_epack[p];
            int sn = pk >> 4;
            int c = pk & 15;
            float2 nh = loadh((size_t)sn * 128 + d2);
            float2 scv = *(const float2*)&sc[c][2 * d2];
            acc.x += nh.x + scv.x;
            acc.y += nh.y + scv.y;
        }
        A2[(size_t)i * 128 + d2] = __floats2half2_rn(acc.x, acc.y);
    }
}

// =================== wmma fp16 GEMM, 2-stage cp.async, BK=32 ================
// (R11 proven-best configuration, byte-identical mainloop)
// BM=128, BN=128, BK=32. 8 warps = 2(M) x 4(N); warp tile 64x32 = 4x2 wmma tiles.
// G==0: g_t1h = half(relu(g_aggh @ W1h + b1))
// G==1: g_zh = half(g_t1h @ W2h)  + fused column sum/sumsq partials (fp32)
#define HLD 40                             // halfs per SMEM row (32 + pad 8) = 80B
#define STG_HALFS (2 * 128 * HLD)          // A + B per stage = 10240 halfs
#define GEMM_SMEM (2 * STG_HALFS * 2)      // 40960 bytes (double buffered)
#define ELD 68                             // epilogue float tile leading dim

template<int G>
__global__ __launch_bounds__(256, 2)
void gemm_wmma(const float* __restrict__ bias, int l) {
    constexpr int K  = (G == 0) ? DD : HID;
    constexpr int NC = (G == 0) ? HID : DD;
    constexpr int NIT = K / 32;

    const __half* __restrict__ A = (G == 0) ? (const __half*)g_aggh : (const __half*)g_t1h;
    const __half* __restrict__ BT =
        ((G == 0) ? (const __half*)g_w1h : (const __half*)g_w2h) + (size_t)l * K * NC;

    extern __shared__ __half smh[];
    __shared__ float ps[4][64];
    __shared__ float pq[4][64];

    const int tid = threadIdx.x;
    const int wid = tid >> 5;
    const int warpM = wid & 1;    // 0..1  (64 rows)
    const int warpN = wid >> 1;   // 0..3  (32 cols)
    const int m0 = blockIdx.y * 128;
    const int n0 = blockIdx.x * 128;

    // staging: thread t -> row = t>>1 (0..127), 32B segment = (t&1)
    const int row = tid >> 1;
    const int seg = tid & 1;

    const uint32_t smBase = smem_u32(smh);
    const uint32_t smA[2] = { smBase + (uint32_t)(row * HLD + seg * 16) * 2u,
                              smBase + (uint32_t)(STG_HALFS + row * HLD + seg * 16) * 2u };
    const uint32_t smB[2] = { smA[0] + 128u * HLD * 2u, smA[1] + 128u * HLD * 2u };
    const __half* gA = A  + (size_t)(m0 + row) * K + seg * 16;
    const __half* gB = BT + (size_t)(n0 + row) * K + seg * 16;

    auto issue_stage = [&](int it, int buf) {
        const __half* a = gA + it * 32;
        const __half* b = gB + it * 32;
        cp16(smA[buf],       a);
        cp16(smA[buf] + 16u, a + 8);
        cp16(smB[buf],       b);
        cp16(smB[buf] + 16u, b + 8);
        CP_COMMIT();
    };

    wmma::fragment<wmma::accumulator, 16, 16, 16, float> acc[4][2];
#pragma unroll
    for (int t = 0; t < 4; t++)
#pragma unroll
        for (int u = 0; u < 2; u++) wmma::fill_fragment(acc[t][u], 0.0f);

    issue_stage(0, 0);
    issue_stage(1, 1);

    for (int it = 0; it < NIT; it++) {
        int buf = it & 1;
        if (it == NIT - 1) CP_WAIT(0); else CP_WAIT(1);
        __syncthreads();

        const __half* As = smh + buf * STG_HALFS;
        const __half* Bs = As + 128 * HLD;
#pragma unroll
        for (int ks = 0; ks < 2; ks++) {
            wmma::fragment<wmma::matrix_a, 16, 16, 16, __half, wmma::row_major> af[4];
            wmma::fragment<wmma::matrix_b, 16, 16, 16, __half, wmma::col_major> bf[2];
#pragma unroll
            for (int t = 0; t < 4; t++)
                wmma::load_matrix_sync(af[t], As + (warpM * 64 + t * 16) * HLD + ks * 16, HLD);
#pragma unroll
            for (int u = 0; u < 2; u++)
                wmma::load_matrix_sync(bf[u], Bs + (warpN * 32 + u * 16) * HLD + ks * 16, HLD);
#pragma unroll
            for (int t = 0; t < 4; t++)
#pragma unroll
                for (int u = 0; u < 2; u++)
                    wmma::mma_sync(acc[t][u], af[t], bf[u], acc[t][u]);
        }

        if (it + 2 < NIT) {
            __syncthreads();              // all warps done reading buf before refill
            issue_stage(it + 2, buf);
        }
    }

    // -------- epilogue: 2 passes of 64 columns via SMEM float tile ----------
    float* ep = (float*)smh;              // 128 x ELD floats = 34816 B <= GEMM_SMEM
    const int coff = seg * 32;
#pragma unroll
    for (int p = 0; p < 2; p++) {
        __syncthreads();
        if ((warpN >> 1) == p) {
#pragma unroll
            for (int t = 0; t < 4; t++)
#pragma unroll
                for (int u = 0; u < 2; u++)
                    wmma::store_matrix_sync(
                        ep + (warpM * 64 + t * 16) * ELD + (warpN & 1) * 32 + u * 16,
                        acc[t][u], ELD, wmma::mem_row_major);
        }
        __syncthreads();

        if (G == 0) {
            const float* srow = ep + row * ELD + coff;
            const float* brow = bias + n0 + p * 64 + coff;
            __half2* crow = (__half2*)(g_t1h + (size_t)(m0 + row) * NC + n0 + p * 64 + coff);
#pragma unroll
            for (int i = 0; i < 16; i++) {
                float2 v = *(const float2*)(srow + 2 * i);
                float2 bp = *(const float2*)(brow + 2 * i);
                crow[i] = __floats2half2_rn(fmaxf(v.x + bp.x, 0.f), fmaxf(v.y + bp.y, 0.f));
            }
        } else {
            // half store of z to g_zh
            const float* srow = ep + row * ELD + coff;
            __half2* crow = (__half2*)(g_zh + (size_t)(m0 + row) * NC + n0 + p * 64 + coff);
#pragma unroll
            for (int i = 0; i < 16; i++) {
                float2 v = *(const float2*)(srow + 2 * i);
                crow[i] = __floats2half2_rn(v.x, v.y);
            }

            // fused column partials from exact fp32 tile (exclude padding rows)
            const int col = tid & 63;
            const int grp = tid >> 6;
            const int rlim = (NN - m0 < 128) ? (NN - m0) : 128;
            float s = 0.f, q = 0.f;
            for (int r = grp * 32; r < grp * 32 + 32; r++) {
                if (r >= rlim) break;
                float v = ep[r * ELD + col];
                s += v; q += v * v;
            }
            ps[grp][col] = s;
            pq[grp][col] = q;
            __syncthreads();
            if (grp == 0) {
                float S = ps[0][col] + ps[1][col] + ps[2][col] + ps[3][col];
                float Q = pq[0][col] + pq[1][col] + pq[2][col] + pq[3][col];
                int cg = n0 + p * 64 + col;
                g_partial2[(size_t)blockIdx.y * 2 * DD + cg] = S;
                g_partial2[(size_t)blockIdx.y * 2 * DD + DD + cg] = Q;
            }
        }
    }
}

// ---------------- BN stats reduce -> affine a,c per column ----------------
__global__ __launch_bounds__(128)
void k_colreduce2(const float* __restrict__ bn_g, const float* __restrict__ bn_b) {
    int d = blockIdx.x;                   // column
    int t = threadIdx.x;
    __shared__ float ss[128], qq[128];
    float s = 0.f, q = 0.f;
    for (int c = t; c < MTILES; c += 128) {
        s += g_partial2[(size_t)c * 2 * DD + d];
        q += g_partial2[(size_t)c * 2 * DD + DD + d];
    }
    ss[t] = s; qq[t] = q;
    __syncthreads();
    for (int o = 64; o > 0; o >>= 1) {
        if (t < o) { ss[t] += ss[t + o]; qq[t] += qq[t + o]; }
        __syncthreads();
    }
    if (t == 0) {
        float mu = ss[0] / (float)NN;
        float var = qq[0] / (float)NN - mu * mu;
        float rstd = rsqrtf(var + BN_EPS);
        float a = rstd * bn_g[d];
        g_stats[d] = a;
        g_stats[DD + d] = bn_b[d] - mu * a;
    }
}

// ---------------- pooling with fused final-layer BN+ReLU ----------------
__device__ __forceinline__ int lower_bound_dev(const int* a, int n, int key) {
    int lo = 0, hi = n;
    while (lo < hi) {
        int mid = (lo + hi) >> 1;
        if (a[mid] < key) lo = mid + 1; else hi = mid;
    }
    return lo;
}

__global__ void k_pool_bn(const int* __restrict__ batch) {
    int b = blockIdx.x;
    int d = threadIdx.x;
    __shared__ int lo_s, hi_s;
    if (d == 0) {
        lo_s = lower_bound_dev(batch, NN, b);
        hi_s = lower_bound_dev(batch, NN, b + 1);
    }
    __syncthreads();
    int lo = lo_s, hi = hi_s;
    const float a = g_stats[d];
    const float c = g_stats[DD + d];
    float s = 0.f;
    for (int i = lo; i < hi; i++) {
        float z = __half2float(g_zh[(size_t)i * DD + d]);
        s += fmaxf(z * a + c, 0.f);
    }
    float cnt = (float)(hi - lo);
    g_pooled[b * DD + d] = s / fmaxf(cnt, 1.f);
}

// ---------------- output MLP ----------------
__global__ void k_out(const float* __restrict__ Wo1, const float* __restrict__ bo1,
                      const float* __restrict__ Wo2, const float* __restrict__ bo2,
                      float* __restrict__ out) {
    int b = blockIdx.x;
    int j = threadIdx.x;
    __shared__ float p[DD];
    __shared__ float r0[128], r1[128];
    p[j] = g_pooled[b * DD + j];
    p[j + 128] = g_pooled[b * DD + 128 + j];
    __syncthreads();
    float acc = bo1[j];
    for (int k = 0; k < DD; k++) acc += p[k] * Wo1[k * 128 + j];
    float hv = (acc > 20.f) ? acc : log1pf(expf(acc));
    r0[j] = hv * Wo2[j * 2 + 0];
    r1[j] = hv * Wo2[j * 2 + 1];
    __syncthreads();
    for (int s = 64; s > 0; s >>= 1) {
        if (j < s) { r0[j] += r0[j + s]; r1[j] += r1[j + s]; }
        __syncthreads();
    }
    if (j == 0) {
        out[b * 2 + 0] = r0[0] + bo2[0];
        out[b * 2 + 1] = r1[0] + bo2[1];
    }
}

// ---------------- launch ----------------
extern "C" void kernel_launch(void* const* d_in, const int* in_sizes, int n_in,
                              void* d_out, int out_size) {
    const int*   x          = (const int*)d_in[0];
    const int*   edge_index = (const int*)d_in[1];
    const int*   edge_attr  = (const int*)d_in[2];
    const int*   batch      = (const int*)d_in[3];
    const float* x_emb1     = (const float*)d_in[4];
    const float* x_emb2     = (const float*)d_in[5];
    const float* edge_emb1  = (const float*)d_in[6];
    const float* edge_emb2  = (const float*)d_in[7];
    const float* W1         = (const float*)d_in[8];
    const float* b1         = (const float*)d_in[9];
    const float* W2         = (const float*)d_in[10];
    const float* b2         = (const float*)d_in[11];  // dropped (BN-invariant)
    const float* bn_g       = (const float*)d_in[12];
    const float* bn_b       = (const float*)d_in[13];
    const float* Wo1        = (const float*)d_in[14];
    const float* bo1        = (const float*)d_in[15];
    const float* Wo2        = (const float*)d_in[16];
    const float* bo2        = (const float*)d_in[17];
    float* out = (float*)d_out;
    (void)b2;

    cudaFuncSetAttribute(gemm_wmma<0>, cudaFuncAttributeMaxDynamicSharedMemorySize, GEMM_SMEM);
    cudaFuncSetAttribute(gemm_wmma<1>, cudaFuncAttributeMaxDynamicSharedMemorySize, GEMM_SMEM);

    // CSR build (parallel scan; packed records scattered directly)
    k_zero_deg<<<(NN + 255) / 256, 256>>>();
    k_hist<<<(EE + 255) / 256, 256>>>(edge_index);
    k_scan1<<<SCAN_NBLK, 256>>>();
    k_scan2<<<1, 512>>>();
    k_scan3<<<SCAN_NBLK, 256>>>();
    k_scatter<<<(EE + 255) / 256, 256>>>(edge_index, edge_attr);
    k_sortseg<<<(NN + 255) / 256, 256>>>();

    // weight transpose -> half (single launch for both W1 and W2)
    k_prep_w<<<(W1_ELEMS + W2_ELEMS + 255) / 256, 256>>>(W1, W2);

    k_init_h<<<NN, DD>>>(x, x_emb1, x_emb2);

    for (int l = 0; l < LL; l++) {
        const float* e1 = edge_emb1 + (size_t)l * 5 * DD;
        const float* e2 = edge_emb2 + (size_t)l * 3 * DD;
        if (l == 0)
            k_agg<0><<<(NN + AGG_NPB - 1) / AGG_NPB, 128>>>(e1, e2);
        else
            k_agg<1><<<(NN + AGG_NPB - 1) / AGG_NPB, 128>>>(e1, e2);
        {   // GEMM1: t1h = half(relu(aggh @ W1 + b1))
            dim3 grid(HID / 128, MTILES);
            gemm_wmma<0><<<grid, 256, GEMM_SMEM>>>(b1 + (size_t)l * HID, l);
        }
        {   // GEMM2: zh = half(t1h @ W2) + fused BN column partials
            dim3 grid(DD / 128, MTILES);
            gemm_wmma<1><<<grid, 256, GEMM_SMEM>>>(b1 + (size_t)l * HID, l);
        }
        k_colreduce2<<<DD, 128>>>(bn_g + (size_t)l * DD, bn_b + (size_t)l * DD);
    }

    k_pool_bn<<<BB, DD>>>(batch);
    k_out<<<BB, 128>>>(Wo1, bo1, Wo2, bo2, out);
}